// round 9
// baseline (speedup 1.0000x reference)
#include <cuda_runtime.h>
#include <math.h>
#include <stdint.h>

// ---------------- problem constants ----------------
#define Bb     2
#define Ss     2048
#define DIMc   2048
#define Hh     16
#define QLORA  1536
#define KVLORA 512
#define NOPEc  128
#define ROPEc  64
#define VDIMc  128
#define QKH    192            // NOPE + ROPE
#define ROWS   (Bb*Ss)        // 4096
#define DF     576            // 512 latent + 64 rope
#define SCALEc 0.07216878364870322f  // 1/sqrt(192)
#define EPSc   1e-6f

// ---------------- scratch (static device arrays; no allocation) ----------------
__device__ float g_qlat[(size_t)ROWS * QLORA];          // 4096 x 1536
__device__ float g_q[(size_t)ROWS * (Hh * QKH)];        // 4096 x 3072
__device__ float g_kv[(size_t)ROWS * DF];               // 4096 x 576
__device__ float g_kfull[(size_t)ROWS * DF];            // 4096 x 576
__device__ float g_qfull[(size_t)ROWS * Hh * DF];       // 4096 x 16 x 576
__device__ float g_ctx[(size_t)ROWS * Hh * KVLORA];     // 4096 x 16 x 512
__device__ float g_attnout[(size_t)ROWS * DIMc];        // 4096 x 2048
__device__ float g_wkvbT[(size_t)Hh * KVLORA * NOPEc];  // 16 x 512 x 128 (transposed nope half)

// ================= tf32 helpers =================
__device__ __forceinline__ uint32_t f2tf(float x) {
    uint32_t r;
    asm("cvt.rna.tf32.f32 %0, %1;" : "=r"(r) : "f"(x));
    return r;
}
__device__ __forceinline__ float4 tf4(float4 v) {
    v.x = __uint_as_float(f2tf(v.x));
    v.y = __uint_as_float(f2tf(v.y));
    v.z = __uint_as_float(f2tf(v.z));
    v.w = __uint_as_float(f2tf(v.w));
    return v;
}
__device__ __forceinline__ void mma_tf32(float* d, const uint32_t* a, const uint32_t* b) {
    asm volatile(
        "mma.sync.aligned.m16n8k8.row.col.f32.tf32.tf32.f32 "
        "{%0,%1,%2,%3}, {%4,%5,%6,%7}, {%8,%9}, {%0,%1,%2,%3};"
        : "+f"(d[0]), "+f"(d[1]), "+f"(d[2]), "+f"(d[3])
        : "r"(a[0]), "r"(a[1]), "r"(a[2]), "r"(a[3]), "r"(b[0]), "r"(b[1]));
}

// ================= tf32 tensor-core GEMM (TB: C = A @ B^T) =================
// 128 threads, 4 warps of 64x64 warp tiles (2x2), 128x128 block tile, BK=16.
// Smem: swizzled row-major  word(m,k) = m*16 + (k ^ ((m>>1)&3)*4).
//   - tile stores: conflict-free STS.128
//   - fragment loads: conflict-free LDS.32
__global__ __launch_bounds__(128) void gemm_tc_kernel(
    const float* __restrict__ A, int lda, long sA_,
    const float* __restrict__ B, int ldb, long sB_,
    float* __restrict__ C, int ldc, long sC_,
    int M, int N, int K)
{
    __shared__ __align__(16) uint32_t sA[2][2048];
    __shared__ __align__(16) uint32_t sB[2][2048];

    int z = blockIdx.z;
    A += (size_t)z * sA_;
    B += (size_t)z * sB_;
    C += (size_t)z * sC_;

    const int tid    = threadIdx.x;
    const int lane   = tid & 31;
    const int warp   = tid >> 5;       // 0..3
    const int warp_m = warp >> 1;      // 0..1
    const int warp_n = warp & 1;       // 0..1
    const int g = lane >> 2, t = lane & 3;
    const int m0 = blockIdx.y * 128;
    const int n0 = blockIdx.x * 128;
    const int KT = K >> 4;

    float acc[4][8][4];
#pragma unroll
    for (int mt = 0; mt < 4; mt++)
#pragma unroll
        for (int nt = 0; nt < 8; nt++)
#pragma unroll
            for (int e = 0; e < 4; e++) acc[mt][nt][e] = 0.f;

    // loader: one row per thread, 4 float4 per tile (full BK=16 row)
    float4 av[4], bv[4];
    const int lr = tid;                // row 0..127

    auto loadT = [&](int kt) {
        int k0 = kt << 4;
        const float* ap = A + (size_t)(m0 + lr) * lda + k0;
#pragma unroll
        for (int i = 0; i < 4; i++) av[i] = *(const float4*)(ap + i * 4);
        if (n0 + lr < N) {
            const float* bp = B + (size_t)(n0 + lr) * ldb + k0;
#pragma unroll
            for (int i = 0; i < 4; i++) bv[i] = *(const float4*)(bp + i * 4);
        } else {
#pragma unroll
            for (int i = 0; i < 4; i++) bv[i] = make_float4(0.f, 0.f, 0.f, 0.f);
        }
    };

    auto storeT = [&](int buf) {
        const int sw = ((lr >> 1) & 3) << 2;
#pragma unroll
        for (int i = 0; i < 4; i++) {
            int xc = (i << 2) ^ sw;
            uint4 ta;
            ta.x = f2tf(av[i].x); ta.y = f2tf(av[i].y);
            ta.z = f2tf(av[i].z); ta.w = f2tf(av[i].w);
            *(uint4*)&sA[buf][lr * 16 + xc] = ta;
            uint4 tb;
            tb.x = f2tf(bv[i].x); tb.y = f2tf(bv[i].y);
            tb.z = f2tf(bv[i].z); tb.w = f2tf(bv[i].w);
            *(uint4*)&sB[buf][lr * 16 + xc] = tb;
        }
    };

    const int fr = (g >> 1) << 2;      // fragment-row swizzle

    auto compute = [&](int buf) {
#pragma unroll
        for (int ks = 0; ks < 2; ks++) {
            const int xk  = ((ks << 3) | t) ^ fr;
            const int xk2 = xk ^ 4;
            uint32_t af[4][4];
            uint32_t bf[8][2];
#pragma unroll
            for (int mt = 0; mt < 4; mt++) {
                int base = (warp_m * 64 + mt * 16 + g) * 16;
                af[mt][0] = sA[buf][base + xk];
                af[mt][1] = sA[buf][base + 128 + xk];
                af[mt][2] = sA[buf][base + xk2];
                af[mt][3] = sA[buf][base + 128 + xk2];
            }
#pragma unroll
            for (int nt = 0; nt < 8; nt++) {
                int base = (warp_n * 64 + nt * 8 + g) * 16;
                bf[nt][0] = sB[buf][base + xk];
                bf[nt][1] = sB[buf][base + xk2];
            }
#pragma unroll
            for (int mt = 0; mt < 4; mt++)
#pragma unroll
                for (int nt = 0; nt < 8; nt++)
                    mma_tf32(acc[mt][nt], af[mt], bf[nt]);
        }
    };

    loadT(0);
    storeT(0);
    __syncthreads();
    if (KT > 1) loadT(1);

    for (int kt = 0; kt < KT; kt++) {
        int cur = kt & 1;
        compute(cur);
        if (kt + 1 < KT) storeT(1 - cur);
        __syncthreads();
        if (kt + 2 < KT) loadT(kt + 2);
    }

    // ---- epilogue ----
#pragma unroll
    for (int mt = 0; mt < 4; mt++) {
        int row0 = m0 + warp_m * 64 + mt * 16 + g;
#pragma unroll
        for (int nt = 0; nt < 8; nt++) {
            int col = n0 + warp_n * 64 + nt * 8 + 2 * t;
            if (col < N) {
                *(float2*)(C + (size_t)row0 * ldc + col) =
                    make_float2(acc[mt][nt][0], acc[mt][nt][1]);
                *(float2*)(C + (size_t)(row0 + 8) * ldc + col) =
                    make_float2(acc[mt][nt][2], acc[mt][nt][3]);
            }
        }
    }
}

// ---------------- transpose wkv_b nope half: out[h][c][d] = wkv_b[h*256+d][c] ----------------
__global__ __launch_bounds__(256) void transpose_wkvb_kernel(
    const float* __restrict__ w, float* __restrict__ out)
{
    __shared__ float tile[32][33];
    int h = blockIdx.z;
    int c0 = blockIdx.x * 32;
    int d0 = blockIdx.y * 32;
    int tx = threadIdx.x & 31, ty = threadIdx.x >> 5;
#pragma unroll
    for (int i = ty; i < 32; i += 8)
        tile[i][tx] = w[((size_t)h * 256 + d0 + i) * KVLORA + c0 + tx];
    __syncthreads();
#pragma unroll
    for (int i = ty; i < 32; i += 8)
        out[((size_t)h * KVLORA + c0 + i) * NOPEc + d0 + tx] = tile[tx][i];
}

// ---------------- RMSNorm (in-place, one block per row) ----------------
__global__ __launch_bounds__(256) void rmsnorm_kernel(
    float* __restrict__ x, const float* __restrict__ w, int L)
{
    __shared__ float sbuf[8];
    int row = blockIdx.x;
    float* xr = x + (size_t)row * L;
    float ss = 0.f;
    for (int i = threadIdx.x; i < L; i += 256) { float v = xr[i]; ss += v * v; }
#pragma unroll
    for (int o = 16; o; o >>= 1) ss += __shfl_xor_sync(0xffffffffu, ss, o);
    int warp = threadIdx.x >> 5, lane = threadIdx.x & 31;
    if (lane == 0) sbuf[warp] = ss;
    __syncthreads();
    if (threadIdx.x == 0) {
        float t = 0.f;
#pragma unroll
        for (int i = 0; i < 8; i++) t += sbuf[i];
        sbuf[0] = rsqrtf(t / (float)L + EPSc);
    }
    __syncthreads();
    float sc = sbuf[0];
    for (int i = threadIdx.x; i < L; i += 256) xr[i] = xr[i] * sc * w[i];
}

// ---------------- kv split: rmsnorm(latent) + rope(k_pe) -> kfull ----------------
__global__ __launch_bounds__(256) void kvprep_kernel(
    const float* __restrict__ kv, const float* __restrict__ w,
    const float* __restrict__ fcos, const float* __restrict__ fsin,
    float* __restrict__ kfull)
{
    __shared__ float sbuf[8];
    int row = blockIdx.x;
    int s = row & (Ss - 1);
    const float* kr = kv + (size_t)row * DF;
    float* kf = kfull + (size_t)row * DF;

    float ss = 0.f;
    for (int i = threadIdx.x; i < KVLORA; i += 256) { float v = kr[i]; ss += v * v; }
#pragma unroll
    for (int o = 16; o; o >>= 1) ss += __shfl_xor_sync(0xffffffffu, ss, o);
    int warp = threadIdx.x >> 5, lane = threadIdx.x & 31;
    if (lane == 0) sbuf[warp] = ss;
    __syncthreads();
    if (threadIdx.x == 0) {
        float t = 0.f;
#pragma unroll
        for (int i = 0; i < 8; i++) t += sbuf[i];
        sbuf[0] = rsqrtf(t / (float)KVLORA + EPSc);
    }
    __syncthreads();
    float sc = sbuf[0];
    for (int i = threadIdx.x; i < KVLORA; i += 256) kf[i] = kr[i] * sc * w[i];

    if (threadIdx.x < 32) {
        int i = threadIdx.x;
        float x0 = kr[KVLORA + 2 * i], x1 = kr[KVLORA + 2 * i + 1];
        float c = fcos[s * 32 + i], sn = fsin[s * 32 + i];
        kf[KVLORA + 2 * i]     = x0 * c - x1 * sn;
        kf[KVLORA + 2 * i + 1] = x0 * sn + x1 * c;
    }
}

// ---------------- rope(q_pe) -> qfull[:, :, 512:576] ----------------
__global__ __launch_bounds__(512) void ropeq_kernel(
    const float* __restrict__ q, const float* __restrict__ fcos,
    const float* __restrict__ fsin, float* __restrict__ qfull)
{
    int row = blockIdx.x;
    int s = row & (Ss - 1);
    int t = threadIdx.x;       // 512 = 16 heads * 32 pairs
    int h = t >> 5, i = t & 31;
    const float* qr = q + (size_t)row * (Hh * QKH) + h * QKH + NOPEc;
    float x0 = qr[2 * i], x1 = qr[2 * i + 1];
    float c = fcos[s * 32 + i], sn = fsin[s * 32 + i];
    float* dst = qfull + ((size_t)row * Hh + h) * DF + KVLORA;
    dst[2 * i]     = x0 * c - x1 * sn;
    dst[2 * i + 1] = x0 * sn + x1 * c;
}

// ---------------- flash attention (tf32 mma, 32q x 32k tiles, 4-way k-split) ----------------
#define KSTR 588
#define PSTR 36
#define ATTN_SMEM_BYTES ((2 * 32 * KSTR + 4 * 32 * PSTR + 64) * 4)

__global__ __launch_bounds__(256, 1) void attn_kernel(
    const float* __restrict__ qfull, const float* __restrict__ kfull,
    float* __restrict__ ctx)
{
    extern __shared__ float sm[];
    float* Qs   = sm;                   // 32 x 588 (tf32)
    float* Ks   = sm + 32 * KSTR;       // 32 x 588 (tf32; cols 0..511 double as V)
    float* Ps   = Ks + 32 * KSTR;       // 4 buffers of 32 x 36 (score partials; buf 0 reused as P)
    float* arow = Ps + 4 * 32 * PSTR;   // 32
    float* lrow = arow + 32;            // 32

    const int tid  = threadIdx.x;
    const int lane = tid & 31, warp = tid >> 5;
    const int g = lane >> 2, t = lane & 3;
    // score roles: 2(m) x 4(k-split); each warp does full n32
    const int wk = warp & 3, wm = warp >> 2;
    const int bh = blockIdx.y;
    const int b = bh >> 4, h = bh & 15;
    const int s0 = blockIdx.x * 32;

    // ---- load Q tile (tf32-rounded) ----
    {
        int qrow = tid >> 3, t8 = tid & 7;
        const float4* src = (const float4*)(qfull + ((size_t)(b * Ss + s0 + qrow) * Hh + h) * DF);
        float4* dst = (float4*)(Qs + qrow * KSTR);
#pragma unroll
        for (int c = 0; c < 18; c++) dst[t8 + c * 8] = tf4(src[t8 + c * 8]);
    }

    float oacc[2][8][4];
#pragma unroll
    for (int mt = 0; mt < 2; mt++)
#pragma unroll
        for (int nt = 0; nt < 8; nt++)
#pragma unroll
            for (int e = 0; e < 4; e++) oacc[mt][nt][e] = 0.f;

    float mreg[4], lreg[4];
#pragma unroll
    for (int ii = 0; ii < 4; ii++) { mreg[ii] = -INFINITY; lreg[ii] = 0.f; }

    const int ntiles = s0 / 32 + 1;
    for (int kt = 0; kt < ntiles; kt++) {
        int t0 = kt * 32;
        // ---- load K tile (tf32-rounded) ----
        {
            int krow = tid >> 3, t8 = tid & 7;
            const float4* src = (const float4*)(kfull + (size_t)(b * Ss + t0 + krow) * DF);
            float4* dst = (float4*)(Ks + krow * KSTR);
#pragma unroll
            for (int c = 0; c < 18; c++) dst[t8 + c * 8] = tf4(src[t8 + c * 8]);
        }
        __syncthreads();

        // ---- scores: warp (wm, wk) -> m16 x n32 tile, k-quarter wk (144 each) ----
        {
            float sacc[4][4];
#pragma unroll
            for (int nt = 0; nt < 4; nt++)
#pragma unroll
                for (int e = 0; e < 4; e++) sacc[nt][e] = 0.f;

            const float* qb0 = Qs + (wm * 16 + g) * KSTR + wk * 144 + t;
#pragma unroll 3
            for (int ks = 0; ks < 18; ks++) {
                const float* qb = qb0 + ks * 8;
                uint32_t a[4];
                a[0] = __float_as_uint(qb[0]);
                a[1] = __float_as_uint(qb[8 * KSTR]);
                a[2] = __float_as_uint(qb[4]);
                a[3] = __float_as_uint(qb[8 * KSTR + 4]);
#pragma unroll
                for (int nt = 0; nt < 4; nt++) {
                    const float* kb = Ks + (nt * 8 + g) * KSTR + wk * 144 + ks * 8 + t;
                    uint32_t bf[2];
                    bf[0] = __float_as_uint(kb[0]);
                    bf[1] = __float_as_uint(kb[4]);
                    mma_tf32(sacc[nt], a, bf);
                }
            }
            float* Pw = Ps + wk * 32 * PSTR;
#pragma unroll
            for (int nt = 0; nt < 4; nt++) {
                int colb = nt * 8 + 2 * t;
                *(float2*)&Pw[(wm * 16 + g) * PSTR + colb] =
                    make_float2(sacc[nt][0], sacc[nt][1]);
                *(float2*)&Pw[(wm * 16 + g + 8) * PSTR + colb] =
                    make_float2(sacc[nt][2], sacc[nt][3]);
            }
        }
        __syncthreads();

        // ---- softmax: warp owns rows 4*warp..+3, lane = key j ----
        {
#pragma unroll
            for (int ii = 0; ii < 4; ii++) {
                int i = warp * 4 + ii;
                float v = (Ps[i * PSTR + lane] +
                           Ps[32 * PSTR + i * PSTR + lane] +
                           Ps[64 * PSTR + i * PSTR + lane] +
                           Ps[96 * PSTR + i * PSTR + lane]) * SCALEc;
                if (t0 + lane > s0 + i) v = -INFINITY;
                float mx = v;
#pragma unroll
                for (int o = 16; o; o >>= 1) mx = fmaxf(mx, __shfl_xor_sync(0xffffffffu, mx, o));
                float mnew = fmaxf(mreg[ii], mx);
                float p = __expf(v - mnew);
                float psum = p;
#pragma unroll
                for (int o = 16; o; o >>= 1) psum += __shfl_xor_sync(0xffffffffu, psum, o);
                float al = __expf(mreg[ii] - mnew);
                lreg[ii] = lreg[ii] * al + psum;
                mreg[ii] = mnew;
                Ps[i * PSTR + lane] = __uint_as_float(f2tf(p));
                if (lane == 0) arow[i] = al;
            }
        }
        __syncthreads();

        // ---- PV: warp owns all 32 rows x cols [warp*64, warp*64+64) ----
        {
#pragma unroll
            for (int mt = 0; mt < 2; mt++) {
                float al0 = arow[mt * 16 + g];
                float al1 = arow[mt * 16 + g + 8];
#pragma unroll
                for (int nt = 0; nt < 8; nt++) {
                    oacc[mt][nt][0] *= al0; oacc[mt][nt][1] *= al0;
                    oacc[mt][nt][2] *= al1; oacc[mt][nt][3] *= al1;
                }
            }
#pragma unroll
            for (int jb = 0; jb < 4; jb++) {
                int j0 = jb * 8;
                uint32_t pa[2][4];
#pragma unroll
                for (int mt = 0; mt < 2; mt++) {
                    const float* pb = Ps + (mt * 16 + g) * PSTR + j0 + t;
                    pa[mt][0] = __float_as_uint(pb[0]);
                    pa[mt][1] = __float_as_uint(pb[8 * PSTR]);
                    pa[mt][2] = __float_as_uint(pb[4]);
                    pa[mt][3] = __float_as_uint(pb[8 * PSTR + 4]);
                }
#pragma unroll
                for (int nt = 0; nt < 8; nt++) {
                    const float* vbp = Ks + (j0 + t) * KSTR + warp * 64 + nt * 8 + g;
                    uint32_t vb[2];
                    vb[0] = __float_as_uint(vbp[0]);
                    vb[1] = __float_as_uint(vbp[4 * KSTR]);
                    mma_tf32(oacc[0][nt], pa[0], vb);
                    mma_tf32(oacc[1][nt], pa[1], vb);
                }
            }
        }
        __syncthreads();
    }

    // ---- publish l, normalize, store ctx ----
    if (lane == 0) {
#pragma unroll
        for (int ii = 0; ii < 4; ii++) lrow[warp * 4 + ii] = lreg[ii];
    }
    __syncthreads();
#pragma unroll
    for (int mt = 0; mt < 2; mt++) {
        int r0 = mt * 16 + g;
        int r1 = mt * 16 + g + 8;
        float inv0 = 1.0f / lrow[r0];
        float inv1 = 1.0f / lrow[r1];
        float* cp0 = ctx + ((size_t)(b * Ss + s0 + r0) * Hh + h) * KVLORA + warp * 64;
        float* cp1 = ctx + ((size_t)(b * Ss + s0 + r1) * Hh + h) * KVLORA + warp * 64;
#pragma unroll
        for (int nt = 0; nt < 8; nt++) {
            int col = nt * 8 + 2 * t;
            *(float2*)(cp0 + col) = make_float2(oacc[mt][nt][0] * inv0, oacc[mt][nt][1] * inv0);
            *(float2*)(cp1 + col) = make_float2(oacc[mt][nt][2] * inv1, oacc[mt][nt][3] * inv1);
        }
    }
}

// ---------------- launch ----------------
extern "C" void kernel_launch(void* const* d_in, const int* in_sizes, int n_in,
                              void* d_out, int out_size)
{
    const float* x     = (const float*)d_in[0];
    const float* fcos  = (const float*)d_in[1];
    const float* fsin  = (const float*)d_in[2];
    // d_in[3] = mask (causal; handled analytically)
    const float* wq_a  = (const float*)d_in[4];
    const float* q_ln  = (const float*)d_in[5];
    const float* wq_b  = (const float*)d_in[6];
    const float* wkv_a = (const float*)d_in[7];
    const float* kv_ln = (const float*)d_in[8];
    const float* wkv_b = (const float*)d_in[9];
    const float* wo    = (const float*)d_in[10];
    float* out = (float*)d_out;

    float *qlat, *q, *kv, *kfull, *qfull, *ctx, *attnout, *wkvbT;
    cudaGetSymbolAddress((void**)&qlat,    g_qlat);
    cudaGetSymbolAddress((void**)&q,       g_q);
    cudaGetSymbolAddress((void**)&kv,      g_kv);
    cudaGetSymbolAddress((void**)&kfull,   g_kfull);
    cudaGetSymbolAddress((void**)&qfull,   g_qfull);
    cudaGetSymbolAddress((void**)&ctx,     g_ctx);
    cudaGetSymbolAddress((void**)&attnout, g_attnout);
    cudaGetSymbolAddress((void**)&wkvbT,   g_wkvbT);

    cudaFuncSetAttribute(attn_kernel, cudaFuncAttributeMaxDynamicSharedMemorySize,
                         ATTN_SMEM_BYTES);

    dim3 gblk(128);
    dim3 blk(256);

    // 0. transpose wkv_b nope half -> wkvbT[h][512][128]
    transpose_wkvb_kernel<<<dim3(KVLORA / 32, NOPEc / 32, Hh), blk>>>(wkv_b, wkvbT);

    // 1. q_lat_pre = x @ wq_a^T      (4096 x 1536, K=2048)
    gemm_tc_kernel<<<dim3(QLORA / 128, ROWS / 128, 1), gblk>>>(
        x, DIMc, 0, wq_a, DIMc, 0, qlat, QLORA, 0, ROWS, QLORA, DIMc);

    // 2. rmsnorm in place
    rmsnorm_kernel<<<ROWS, 256>>>(qlat, q_ln, QLORA);

    // 3. q = q_lat @ wq_b^T          (4096 x 3072, K=1536)
    gemm_tc_kernel<<<dim3((Hh * QKH) / 128, ROWS / 128, 1), gblk>>>(
        qlat, QLORA, 0, wq_b, QLORA, 0, q, Hh * QKH, 0, ROWS, Hh * QKH, QLORA);

    // 4. kv = x @ wkv_a^T            (4096 x 576, K=2048)
    gemm_tc_kernel<<<dim3((DF + 127) / 128, ROWS / 128, 1), gblk>>>(
        x, DIMc, 0, wkv_a, DIMc, 0, kv, DF, 0, ROWS, DF, DIMc);

    // 5. kfull = [rmsnorm(kv_lat), rope(k_pe)]
    kvprep_kernel<<<ROWS, 256>>>(kv, kv_ln, fcos, fsin, kfull);

    // 6. q-absorb per head: qfull[:, h, :512] = q_nope_h @ wkvbT[h]^T (batched over heads)
    gemm_tc_kernel<<<dim3(KVLORA / 128, ROWS / 128, Hh), gblk>>>(
        q, Hh * QKH, QKH,
        wkvbT, NOPEc, (long)KVLORA * NOPEc,
        qfull, Hh * DF, DF,
        ROWS, KVLORA, NOPEc);

    // 7. qfull[:, h, 512:576] = rope(q_pe)
    ropeq_kernel<<<ROWS, 512>>>(q, fcos, fsin, qfull);

    // 8. flash attention -> ctx (B,S,H,512)
    attn_kernel<<<dim3(Ss / 32, Bb * Hh), 256, ATTN_SMEM_BYTES>>>(qfull, kfull, ctx);

    // 9. per-head out-proj: attnout[:, h*128:(h+1)*128] = ctx_h @ wkv_b3[h, 128:256, :]^T
    gemm_tc_kernel<<<dim3(1, ROWS / 128, Hh), gblk>>>(
        ctx, Hh * KVLORA, KVLORA,
        wkv_b + (size_t)NOPEc * KVLORA, KVLORA, (long)(NOPEc + VDIMc) * KVLORA,
        attnout, DIMc, VDIMc,
        ROWS, VDIMc, KVLORA);

    // 10. out = attnout @ wo^T       (4096 x 2048, K=2048)
    gemm_tc_kernel<<<dim3(DIMc / 128, ROWS / 128, 1), gblk>>>(
        attnout, DIMc, 0, wo, DIMc, 0, out, DIMc, 0, ROWS, DIMc, DIMc);
}

// round 10
// speedup vs baseline: 1.1964x; 1.1964x over previous
#include <cuda_runtime.h>
#include <math.h>
#include <stdint.h>

// ---------------- problem constants ----------------
#define Bb     2
#define Ss     2048
#define DIMc   2048
#define Hh     16
#define QLORA  1536
#define KVLORA 512
#define NOPEc  128
#define ROPEc  64
#define VDIMc  128
#define QKH    192            // NOPE + ROPE
#define ROWS   (Bb*Ss)        // 4096
#define DF     576            // 512 latent + 64 rope
#define SCALEc 0.07216878364870322f  // 1/sqrt(192)
#define EPSc   1e-6f

// ---------------- scratch (static device arrays; no allocation) ----------------
__device__ float g_qlat[(size_t)ROWS * QLORA];          // 4096 x 1536
__device__ float g_q[(size_t)ROWS * (Hh * QKH)];        // 4096 x 3072
__device__ float g_kv[(size_t)ROWS * DF];               // 4096 x 576
__device__ float g_kfull[(size_t)ROWS * DF];            // 4096 x 576
__device__ float g_qfull[(size_t)ROWS * Hh * DF];       // 4096 x 16 x 576
__device__ float g_ctx[(size_t)ROWS * Hh * KVLORA];     // 4096 x 16 x 512
__device__ float g_attnout[(size_t)ROWS * DIMc];        // 4096 x 2048
__device__ float g_wkvbT[(size_t)Hh * KVLORA * NOPEc];  // 16 x 512 x 128 (transposed nope half)

// ================= tf32 helpers =================
__device__ __forceinline__ uint32_t f2tf(float x) {
    uint32_t r;
    asm("cvt.rna.tf32.f32 %0, %1;" : "=r"(r) : "f"(x));
    return r;
}
__device__ __forceinline__ float4 tf4(float4 v) {
    v.x = __uint_as_float(f2tf(v.x));
    v.y = __uint_as_float(f2tf(v.y));
    v.z = __uint_as_float(f2tf(v.z));
    v.w = __uint_as_float(f2tf(v.w));
    return v;
}
__device__ __forceinline__ void mma_tf32(float* d, const uint32_t* a, const uint32_t* b) {
    asm volatile(
        "mma.sync.aligned.m16n8k8.row.col.f32.tf32.tf32.f32 "
        "{%0,%1,%2,%3}, {%4,%5,%6,%7}, {%8,%9}, {%0,%1,%2,%3};"
        : "+f"(d[0]), "+f"(d[1]), "+f"(d[2]), "+f"(d[3])
        : "r"(a[0]), "r"(a[1]), "r"(a[2]), "r"(a[3]), "r"(b[0]), "r"(b[1]));
}

// ================= tf32 tensor-core GEMM (TB: C = A @ B^T) =================
// 256 threads, 8 warps (2x4), 128x128 block tile, BK=16, warp tile 64x32.
// (R6/R7-verified config: 125 regs, 2 CTAs/SM.)
// Smem: swizzled row-major  word(m,k) = m*16 + (k ^ ((m>>1)&3)*4).
//   - tile stores: conflict-free STS.128
//   - fragment loads: conflict-free LDS.32
__global__ __launch_bounds__(256) void gemm_tc_kernel(
    const float* __restrict__ A, int lda, long sA_,
    const float* __restrict__ B, int ldb, long sB_,
    float* __restrict__ C, int ldc, long sC_,
    int M, int N, int K)
{
    __shared__ __align__(16) uint32_t sA[2][2048];
    __shared__ __align__(16) uint32_t sB[2][2048];

    int z = blockIdx.z;
    A += (size_t)z * sA_;
    B += (size_t)z * sB_;
    C += (size_t)z * sC_;

    const int tid    = threadIdx.x;
    const int lane   = tid & 31;
    const int warp   = tid >> 5;
    const int warp_m = warp >> 2;      // 0..1
    const int warp_n = warp & 3;       // 0..3
    const int g = lane >> 2, t = lane & 3;
    const int m0 = blockIdx.y * 128;
    const int n0 = blockIdx.x * 128;
    const int KT = K >> 4;

    float acc[4][4][4];
#pragma unroll
    for (int mt = 0; mt < 4; mt++)
#pragma unroll
        for (int nt = 0; nt < 4; nt++)
#pragma unroll
            for (int e = 0; e < 4; e++) acc[mt][nt][e] = 0.f;

    float4 av[2], bv[2];
    const int lr0 = tid >> 2;          // row 0..63 (pass 0), +64 (pass 1)
    const int lkc = (tid & 3) << 2;    // k offset 0/4/8/12

    auto loadT = [&](int kt) {
        int k0 = kt << 4;
#pragma unroll
        for (int i = 0; i < 2; i++) {
            int r = lr0 + i * 64;
            av[i] = *(const float4*)(A + (size_t)(m0 + r) * lda + k0 + lkc);
            float4 v = make_float4(0.f, 0.f, 0.f, 0.f);
            if (n0 + r < N) v = *(const float4*)(B + (size_t)(n0 + r) * ldb + k0 + lkc);
            bv[i] = v;
        }
    };

    auto storeT = [&](int buf) {
#pragma unroll
        for (int i = 0; i < 2; i++) {
            int r = lr0 + i * 64;
            int xc = lkc ^ (((r >> 1) & 3) << 2);
            uint4 ta;
            ta.x = f2tf(av[i].x); ta.y = f2tf(av[i].y);
            ta.z = f2tf(av[i].z); ta.w = f2tf(av[i].w);
            *(uint4*)&sA[buf][r * 16 + xc] = ta;
            uint4 tb;
            tb.x = f2tf(bv[i].x); tb.y = f2tf(bv[i].y);
            tb.z = f2tf(bv[i].z); tb.w = f2tf(bv[i].w);
            *(uint4*)&sB[buf][r * 16 + xc] = tb;
        }
    };

    const int fr = (g >> 1) << 2;      // fragment-row swizzle

    auto compute = [&](int buf) {
#pragma unroll
        for (int ks = 0; ks < 2; ks++) {
            const int xk  = ((ks << 3) | t) ^ fr;
            const int xk2 = xk ^ 4;
            uint32_t af[4][4];
            uint32_t bf[4][2];
#pragma unroll
            for (int mt = 0; mt < 4; mt++) {
                int base = (warp_m * 64 + mt * 16 + g) * 16;
                af[mt][0] = sA[buf][base + xk];
                af[mt][1] = sA[buf][base + 128 + xk];
                af[mt][2] = sA[buf][base + xk2];
                af[mt][3] = sA[buf][base + 128 + xk2];
            }
#pragma unroll
            for (int nt = 0; nt < 4; nt++) {
                int base = (warp_n * 32 + nt * 8 + g) * 16;
                bf[nt][0] = sB[buf][base + xk];
                bf[nt][1] = sB[buf][base + xk2];
            }
#pragma unroll
            for (int mt = 0; mt < 4; mt++)
#pragma unroll
                for (int nt = 0; nt < 4; nt++)
                    mma_tf32(acc[mt][nt], af[mt], bf[nt]);
        }
    };

    loadT(0);
    storeT(0);
    __syncthreads();
    if (KT > 1) loadT(1);

    for (int kt = 0; kt < KT; kt++) {
        int cur = kt & 1;
        compute(cur);
        if (kt + 1 < KT) storeT(1 - cur);
        __syncthreads();
        if (kt + 2 < KT) loadT(kt + 2);
    }

    // ---- epilogue ----
#pragma unroll
    for (int mt = 0; mt < 4; mt++) {
        int row0 = m0 + warp_m * 64 + mt * 16 + g;
#pragma unroll
        for (int nt = 0; nt < 4; nt++) {
            int col = n0 + warp_n * 32 + nt * 8 + 2 * t;
            if (col < N) {
                *(float2*)(C + (size_t)row0 * ldc + col) =
                    make_float2(acc[mt][nt][0], acc[mt][nt][1]);
                *(float2*)(C + (size_t)(row0 + 8) * ldc + col) =
                    make_float2(acc[mt][nt][2], acc[mt][nt][3]);
            }
        }
    }
}

// ---------------- transpose wkv_b nope half: out[h][c][d] = wkv_b[h*256+d][c] ----------------
__global__ __launch_bounds__(256) void transpose_wkvb_kernel(
    const float* __restrict__ w, float* __restrict__ out)
{
    __shared__ float tile[32][33];
    int h = blockIdx.z;
    int c0 = blockIdx.x * 32;
    int d0 = blockIdx.y * 32;
    int tx = threadIdx.x & 31, ty = threadIdx.x >> 5;
#pragma unroll
    for (int i = ty; i < 32; i += 8)
        tile[i][tx] = w[((size_t)h * 256 + d0 + i) * KVLORA + c0 + tx];
    __syncthreads();
#pragma unroll
    for (int i = ty; i < 32; i += 8)
        out[((size_t)h * KVLORA + c0 + i) * NOPEc + d0 + tx] = tile[tx][i];
}

// ---------------- RMSNorm (in-place, one block per row) ----------------
__global__ __launch_bounds__(256) void rmsnorm_kernel(
    float* __restrict__ x, const float* __restrict__ w, int L)
{
    __shared__ float sbuf[8];
    int row = blockIdx.x;
    float* xr = x + (size_t)row * L;
    float ss = 0.f;
    for (int i = threadIdx.x; i < L; i += 256) { float v = xr[i]; ss += v * v; }
#pragma unroll
    for (int o = 16; o; o >>= 1) ss += __shfl_xor_sync(0xffffffffu, ss, o);
    int warp = threadIdx.x >> 5, lane = threadIdx.x & 31;
    if (lane == 0) sbuf[warp] = ss;
    __syncthreads();
    if (threadIdx.x == 0) {
        float t = 0.f;
#pragma unroll
        for (int i = 0; i < 8; i++) t += sbuf[i];
        sbuf[0] = rsqrtf(t / (float)L + EPSc);
    }
    __syncthreads();
    float sc = sbuf[0];
    for (int i = threadIdx.x; i < L; i += 256) xr[i] = xr[i] * sc * w[i];
}

// ---------------- kv split: rmsnorm(latent) + rope(k_pe) -> kfull ----------------
__global__ __launch_bounds__(256) void kvprep_kernel(
    const float* __restrict__ kv, const float* __restrict__ w,
    const float* __restrict__ fcos, const float* __restrict__ fsin,
    float* __restrict__ kfull)
{
    __shared__ float sbuf[8];
    int row = blockIdx.x;
    int s = row & (Ss - 1);
    const float* kr = kv + (size_t)row * DF;
    float* kf = kfull + (size_t)row * DF;

    float ss = 0.f;
    for (int i = threadIdx.x; i < KVLORA; i += 256) { float v = kr[i]; ss += v * v; }
#pragma unroll
    for (int o = 16; o; o >>= 1) ss += __shfl_xor_sync(0xffffffffu, ss, o);
    int warp = threadIdx.x >> 5, lane = threadIdx.x & 31;
    if (lane == 0) sbuf[warp] = ss;
    __syncthreads();
    if (threadIdx.x == 0) {
        float t = 0.f;
#pragma unroll
        for (int i = 0; i < 8; i++) t += sbuf[i];
        sbuf[0] = rsqrtf(t / (float)KVLORA + EPSc);
    }
    __syncthreads();
    float sc = sbuf[0];
    for (int i = threadIdx.x; i < KVLORA; i += 256) kf[i] = kr[i] * sc * w[i];

    if (threadIdx.x < 32) {
        int i = threadIdx.x;
        float x0 = kr[KVLORA + 2 * i], x1 = kr[KVLORA + 2 * i + 1];
        float c = fcos[s * 32 + i], sn = fsin[s * 32 + i];
        kf[KVLORA + 2 * i]     = x0 * c - x1 * sn;
        kf[KVLORA + 2 * i + 1] = x0 * sn + x1 * c;
    }
}

// ---------------- rope(q_pe) -> qfull[:, :, 512:576] ----------------
__global__ __launch_bounds__(512) void ropeq_kernel(
    const float* __restrict__ q, const float* __restrict__ fcos,
    const float* __restrict__ fsin, float* __restrict__ qfull)
{
    int row = blockIdx.x;
    int s = row & (Ss - 1);
    int t = threadIdx.x;       // 512 = 16 heads * 32 pairs
    int h = t >> 5, i = t & 31;
    const float* qr = q + (size_t)row * (Hh * QKH) + h * QKH + NOPEc;
    float x0 = qr[2 * i], x1 = qr[2 * i + 1];
    float c = fcos[s * 32 + i], sn = fsin[s * 32 + i];
    float* dst = qfull + ((size_t)row * Hh + h) * DF + KVLORA;
    dst[2 * i]     = x0 * c - x1 * sn;
    dst[2 * i + 1] = x0 * sn + x1 * c;
}

// ---------------- flash attention (tf32 mma, 32q x 32k tiles, 4-way k-split) ----------------
// R8-verified attention variant (passed with rel_err 6.3478e-4).
#define KSTR 588
#define PSTR 36
#define ATTN_SMEM_BYTES ((2 * 32 * KSTR + 4 * 32 * PSTR + 64) * 4)

__global__ __launch_bounds__(256, 1) void attn_kernel(
    const float* __restrict__ qfull, const float* __restrict__ kfull,
    float* __restrict__ ctx)
{
    extern __shared__ float sm[];
    float* Qs   = sm;                   // 32 x 588 (tf32)
    float* Ks   = sm + 32 * KSTR;       // 32 x 588 (tf32; cols 0..511 double as V)
    float* Ps   = Ks + 32 * KSTR;       // 4 buffers of 32 x 36 (score partials; buf 0 reused as P)
    float* arow = Ps + 4 * 32 * PSTR;   // 32
    float* lrow = arow + 32;            // 32

    const int tid  = threadIdx.x;
    const int lane = tid & 31, warp = tid >> 5;
    const int g = lane >> 2, t = lane & 3;
    // score roles: 2(m) x 4(k-split); each warp does full n32
    const int wk = warp & 3, wm = warp >> 2;
    const int bh = blockIdx.y;
    const int b = bh >> 4, h = bh & 15;
    const int s0 = blockIdx.x * 32;

    // ---- load Q tile (tf32-rounded) ----
    {
        int qrow = tid >> 3, t8 = tid & 7;
        const float4* src = (const float4*)(qfull + ((size_t)(b * Ss + s0 + qrow) * Hh + h) * DF);
        float4* dst = (float4*)(Qs + qrow * KSTR);
#pragma unroll
        for (int c = 0; c < 18; c++) dst[t8 + c * 8] = tf4(src[t8 + c * 8]);
    }

    float oacc[2][8][4];
#pragma unroll
    for (int mt = 0; mt < 2; mt++)
#pragma unroll
        for (int nt = 0; nt < 8; nt++)
#pragma unroll
            for (int e = 0; e < 4; e++) oacc[mt][nt][e] = 0.f;

    float mreg[4], lreg[4];
#pragma unroll
    for (int ii = 0; ii < 4; ii++) { mreg[ii] = -INFINITY; lreg[ii] = 0.f; }

    const int ntiles = s0 / 32 + 1;
    for (int kt = 0; kt < ntiles; kt++) {
        int t0 = kt * 32;
        // ---- load K tile (tf32-rounded) ----
        {
            int krow = tid >> 3, t8 = tid & 7;
            const float4* src = (const float4*)(kfull + (size_t)(b * Ss + t0 + krow) * DF);
            float4* dst = (float4*)(Ks + krow * KSTR);
#pragma unroll
            for (int c = 0; c < 18; c++) dst[t8 + c * 8] = tf4(src[t8 + c * 8]);
        }
        __syncthreads();

        // ---- scores: warp (wm, wk) -> m16 x n32 tile, k-quarter wk (144 each) ----
        {
            float sacc[4][4];
#pragma unroll
            for (int nt = 0; nt < 4; nt++)
#pragma unroll
                for (int e = 0; e < 4; e++) sacc[nt][e] = 0.f;

            const float* qb0 = Qs + (wm * 16 + g) * KSTR + wk * 144 + t;
#pragma unroll 3
            for (int ks = 0; ks < 18; ks++) {
                const float* qb = qb0 + ks * 8;
                uint32_t a[4];
                a[0] = __float_as_uint(qb[0]);
                a[1] = __float_as_uint(qb[8 * KSTR]);
                a[2] = __float_as_uint(qb[4]);
                a[3] = __float_as_uint(qb[8 * KSTR + 4]);
#pragma unroll
                for (int nt = 0; nt < 4; nt++) {
                    const float* kb = Ks + (nt * 8 + g) * KSTR + wk * 144 + ks * 8 + t;
                    uint32_t bf[2];
                    bf[0] = __float_as_uint(kb[0]);
                    bf[1] = __float_as_uint(kb[4]);
                    mma_tf32(sacc[nt], a, bf);
                }
            }
            float* Pw = Ps + wk * 32 * PSTR;
#pragma unroll
            for (int nt = 0; nt < 4; nt++) {
                int colb = nt * 8 + 2 * t;
                *(float2*)&Pw[(wm * 16 + g) * PSTR + colb] =
                    make_float2(sacc[nt][0], sacc[nt][1]);
                *(float2*)&Pw[(wm * 16 + g + 8) * PSTR + colb] =
                    make_float2(sacc[nt][2], sacc[nt][3]);
            }
        }
        __syncthreads();

        // ---- softmax: warp owns rows 4*warp..+3, lane = key j ----
        {
#pragma unroll
            for (int ii = 0; ii < 4; ii++) {
                int i = warp * 4 + ii;
                float v = (Ps[i * PSTR + lane] +
                           Ps[32 * PSTR + i * PSTR + lane] +
                           Ps[64 * PSTR + i * PSTR + lane] +
                           Ps[96 * PSTR + i * PSTR + lane]) * SCALEc;
                if (t0 + lane > s0 + i) v = -INFINITY;
                float mx = v;
#pragma unroll
                for (int o = 16; o; o >>= 1) mx = fmaxf(mx, __shfl_xor_sync(0xffffffffu, mx, o));
                float mnew = fmaxf(mreg[ii], mx);
                float p = __expf(v - mnew);
                float psum = p;
#pragma unroll
                for (int o = 16; o; o >>= 1) psum += __shfl_xor_sync(0xffffffffu, psum, o);
                float al = __expf(mreg[ii] - mnew);
                lreg[ii] = lreg[ii] * al + psum;
                mreg[ii] = mnew;
                Ps[i * PSTR + lane] = __uint_as_float(f2tf(p));
                if (lane == 0) arow[i] = al;
            }
        }
        __syncthreads();

        // ---- PV: warp owns all 32 rows x cols [warp*64, warp*64+64) ----
        {
#pragma unroll
            for (int mt = 0; mt < 2; mt++) {
                float al0 = arow[mt * 16 + g];
                float al1 = arow[mt * 16 + g + 8];
#pragma unroll
                for (int nt = 0; nt < 8; nt++) {
                    oacc[mt][nt][0] *= al0; oacc[mt][nt][1] *= al0;
                    oacc[mt][nt][2] *= al1; oacc[mt][nt][3] *= al1;
                }
            }
#pragma unroll
            for (int jb = 0; jb < 4; jb++) {
                int j0 = jb * 8;
                uint32_t pa[2][4];
#pragma unroll
                for (int mt = 0; mt < 2; mt++) {
                    const float* pb = Ps + (mt * 16 + g) * PSTR + j0 + t;
                    pa[mt][0] = __float_as_uint(pb[0]);
                    pa[mt][1] = __float_as_uint(pb[8 * PSTR]);
                    pa[mt][2] = __float_as_uint(pb[4]);
                    pa[mt][3] = __float_as_uint(pb[8 * PSTR + 4]);
                }
#pragma unroll
                for (int nt = 0; nt < 8; nt++) {
                    const float* vbp = Ks + (j0 + t) * KSTR + warp * 64 + nt * 8 + g;
                    uint32_t vb[2];
                    vb[0] = __float_as_uint(vbp[0]);
                    vb[1] = __float_as_uint(vbp[4 * KSTR]);
                    mma_tf32(oacc[0][nt], pa[0], vb);
                    mma_tf32(oacc[1][nt], pa[1], vb);
                }
            }
        }
        __syncthreads();
    }

    // ---- publish l, normalize, store ctx ----
    if (lane == 0) {
#pragma unroll
        for (int ii = 0; ii < 4; ii++) lrow[warp * 4 + ii] = lreg[ii];
    }
    __syncthreads();
#pragma unroll
    for (int mt = 0; mt < 2; mt++) {
        int r0 = mt * 16 + g;
        int r1 = mt * 16 + g + 8;
        float inv0 = 1.0f / lrow[r0];
        float inv1 = 1.0f / lrow[r1];
        float* cp0 = ctx + ((size_t)(b * Ss + s0 + r0) * Hh + h) * KVLORA + warp * 64;
        float* cp1 = ctx + ((size_t)(b * Ss + s0 + r1) * Hh + h) * KVLORA + warp * 64;
#pragma unroll
        for (int nt = 0; nt < 8; nt++) {
            int col = nt * 8 + 2 * t;
            *(float2*)(cp0 + col) = make_float2(oacc[mt][nt][0] * inv0, oacc[mt][nt][1] * inv0);
            *(float2*)(cp1 + col) = make_float2(oacc[mt][nt][2] * inv1, oacc[mt][nt][3] * inv1);
        }
    }
}

// ---------------- launch ----------------
extern "C" void kernel_launch(void* const* d_in, const int* in_sizes, int n_in,
                              void* d_out, int out_size)
{
    const float* x     = (const float*)d_in[0];
    const float* fcos  = (const float*)d_in[1];
    const float* fsin  = (const float*)d_in[2];
    // d_in[3] = mask (causal; handled analytically)
    const float* wq_a  = (const float*)d_in[4];
    const float* q_ln  = (const float*)d_in[5];
    const float* wq_b  = (const float*)d_in[6];
    const float* wkv_a = (const float*)d_in[7];
    const float* kv_ln = (const float*)d_in[8];
    const float* wkv_b = (const float*)d_in[9];
    const float* wo    = (const float*)d_in[10];
    float* out = (float*)d_out;

    float *qlat, *q, *kv, *kfull, *qfull, *ctx, *attnout, *wkvbT;
    cudaGetSymbolAddress((void**)&qlat,    g_qlat);
    cudaGetSymbolAddress((void**)&q,       g_q);
    cudaGetSymbolAddress((void**)&kv,      g_kv);
    cudaGetSymbolAddress((void**)&kfull,   g_kfull);
    cudaGetSymbolAddress((void**)&qfull,   g_qfull);
    cudaGetSymbolAddress((void**)&ctx,     g_ctx);
    cudaGetSymbolAddress((void**)&attnout, g_attnout);
    cudaGetSymbolAddress((void**)&wkvbT,   g_wkvbT);

    cudaFuncSetAttribute(attn_kernel, cudaFuncAttributeMaxDynamicSharedMemorySize,
                         ATTN_SMEM_BYTES);

    dim3 blk(256);

    // 0. transpose wkv_b nope half -> wkvbT[h][512][128]
    transpose_wkvb_kernel<<<dim3(KVLORA / 32, NOPEc / 32, Hh), blk>>>(wkv_b, wkvbT);

    // 1. q_lat_pre = x @ wq_a^T      (4096 x 1536, K=2048)
    gemm_tc_kernel<<<dim3(QLORA / 128, ROWS / 128, 1), blk>>>(
        x, DIMc, 0, wq_a, DIMc, 0, qlat, QLORA, 0, ROWS, QLORA, DIMc);

    // 2. rmsnorm in place
    rmsnorm_kernel<<<ROWS, 256>>>(qlat, q_ln, QLORA);

    // 3. q = q_lat @ wq_b^T          (4096 x 3072, K=1536)
    gemm_tc_kernel<<<dim3((Hh * QKH) / 128, ROWS / 128, 1), blk>>>(
        qlat, QLORA, 0, wq_b, QLORA, 0, q, Hh * QKH, 0, ROWS, Hh * QKH, QLORA);

    // 4. kv = x @ wkv_a^T            (4096 x 576, K=2048)
    gemm_tc_kernel<<<dim3((DF + 127) / 128, ROWS / 128, 1), blk>>>(
        x, DIMc, 0, wkv_a, DIMc, 0, kv, DF, 0, ROWS, DF, DIMc);

    // 5. kfull = [rmsnorm(kv_lat), rope(k_pe)]
    kvprep_kernel<<<ROWS, 256>>>(kv, kv_ln, fcos, fsin, kfull);

    // 6. q-absorb per head: qfull[:, h, :512] = q_nope_h @ wkvbT[h]^T (batched over heads)
    gemm_tc_kernel<<<dim3(KVLORA / 128, ROWS / 128, Hh), blk>>>(
        q, Hh * QKH, QKH,
        wkvbT, NOPEc, (long)KVLORA * NOPEc,
        qfull, Hh * DF, DF,
        ROWS, KVLORA, NOPEc);

    // 7. qfull[:, h, 512:576] = rope(q_pe)
    ropeq_kernel<<<ROWS, 512>>>(q, fcos, fsin, qfull);

    // 8. flash attention -> ctx (B,S,H,512)
    attn_kernel<<<dim3(Ss / 32, Bb * Hh), 256, ATTN_SMEM_BYTES>>>(qfull, kfull, ctx);

    // 9. per-head out-proj: attnout[:, h*128:(h+1)*128] = ctx_h @ wkv_b3[h, 128:256, :]^T
    gemm_tc_kernel<<<dim3(1, ROWS / 128, Hh), blk>>>(
        ctx, Hh * KVLORA, KVLORA,
        wkv_b + (size_t)NOPEc * KVLORA, KVLORA, (long)(NOPEc + VDIMc) * KVLORA,
        attnout, DIMc, VDIMc,
        ROWS, VDIMc, KVLORA);

    // 10. out = attnout @ wo^T       (4096 x 2048, K=2048)
    gemm_tc_kernel<<<dim3(DIMc / 128, ROWS / 128, 1), blk>>>(
        attnout, DIMc, 0, wo, DIMc, 0, out, DIMc, 0, ROWS, DIMc, DIMc);
}